// round 8
// baseline (speedup 1.0000x reference)
#include <cuda_runtime.h>
#include <cuda_bf16.h>
#include <cuda_fp16.h>
#include <cstdint>

// ---------------- problem constants ----------------
#define B_TOK   8192
#define IN_DIM  512
#define HID     2048
#define NCLS    1000
#define NCLS_P  1024      // padded N for layer 3
#define NEXP    4
#define RH      256
#define CAP     8192      // per-expert token capacity

// ---------------- static scratch (no allocs allowed) ----------------
__device__ int8_t        d_xq [B_TOK * IN_DIM];                 // sign(x) in s8
__device__ int8_t        d_w1q[NEXP * HID * IN_DIM];
__device__ int8_t        d_w2q[(long)NEXP * HID * HID];
__device__ int8_t        d_w3q[(long)NEXP * NCLS_P * HID];
__device__ __half        d_h  [(long)NEXP * CAP * HID];         // compact, fp16-exact ints
__device__ int8_t        d_a  [(long)NEXP * CAP * HID];         // {0,1} s8
__device__ __half        d_eo [(long)NEXP * CAP * NCLS_P];      // fp16-exact ints
__device__ float         d_r1 [B_TOK * RH];
__device__ float         d_r2 [B_TOK * (RH/2)];
__device__ int           d_topi[B_TOK * 2];
__device__ float         d_gate[B_TOK * 2];
__device__ int           d_cnt [NEXP];
__device__ int           d_list[NEXP * CAP];     // expert -> token ids
__device__ int           d_slot[B_TOK * 2];      // (token,k) -> slot in expert
__device__ float         d_partial[3 * 4 * 128];
__device__ float         d_wmean[12];

// ---------------- weight mean (deterministic 2-stage) ----------------
__global__ __launch_bounds__(256) void wsum_partial_kernel(
    const float* __restrict__ W, long perE, float* __restrict__ partial)
{
    long e = blockIdx.y;
    const float* base = W + e * perE;
    float s = 0.f;
    for (long i = (long)blockIdx.x * 256 + threadIdx.x; i < perE; i += (long)gridDim.x * 256)
        s += base[i];
    #pragma unroll
    for (int o = 16; o; o >>= 1) s += __shfl_xor_sync(0xffffffffu, s, o);
    __shared__ float sh[8];
    if ((threadIdx.x & 31) == 0) sh[threadIdx.x >> 5] = s;
    __syncthreads();
    if (threadIdx.x == 0) {
        float S = 0.f;
        #pragma unroll
        for (int i = 0; i < 8; i++) S += sh[i];
        partial[e * 128 + blockIdx.x] = S;
    }
}

__global__ void wmean_final_kernel(const float* __restrict__ partial, float* __restrict__ wmean)
{
    int bx = blockIdx.x;                 // 12 blocks: layer = bx/4, expert = bx%4
    int layer = bx >> 2;
    const long counts[3] = {(long)HID * IN_DIM, (long)HID * HID, (long)NCLS * HID};
    float s = partial[bx * 128 + threadIdx.x];   // blockDim = 128
    #pragma unroll
    for (int o = 16; o; o >>= 1) s += __shfl_xor_sync(0xffffffffu, s, o);
    __shared__ float sh[4];
    if ((threadIdx.x & 31) == 0) sh[threadIdx.x >> 5] = s;
    __syncthreads();
    if (threadIdx.x == 0)
        wmean[bx] = (sh[0] + sh[1] + sh[2] + sh[3]) / (float)counts[layer];
}

// ---------------- quantize weights: sign(w - mean) -> s8 (pad rows -> 0) ------
__global__ __launch_bounds__(256) void quantW_kernel(
    const float* __restrict__ w, const float* __restrict__ means,
    int Oin, int Oout, int K, int8_t* __restrict__ out, long total)
{
    long i = (long)blockIdx.x * 256 + threadIdx.x;
    if (i >= total) return;
    int k = (int)(i % K);
    long t = i / K;
    int o = (int)(t % Oout);
    int e = (int)(t / Oout);
    int q = 0;
    if (o < Oin) {
        float v = w[((long)e * Oin + o) * K + k] - means[e];
        q = (v > 0.f) - (v < 0.f);
    }
    out[i] = (int8_t)q;
}

__global__ __launch_bounds__(256) void quantX_kernel(
    const float* __restrict__ x, int8_t* __restrict__ out, long total)
{
    long i = (long)blockIdx.x * 256 + threadIdx.x;
    if (i >= total) return;
    float v = x[i];
    out[i] = (int8_t)((v > 0.f) - (v < 0.f));
}

// ---------------- routing list build ------------------------------------------
__global__ void zero_cnt_kernel(int* cnt) { if (threadIdx.x < NEXP) cnt[threadIdx.x] = 0; }

__global__ __launch_bounds__(256) void build_lists_kernel(
    const int* __restrict__ topi, int* __restrict__ cnt,
    int* __restrict__ list, int* __restrict__ slot)
{
    int b = blockIdx.x * 256 + threadIdx.x;
    if (b >= B_TOK) return;
    #pragma unroll
    for (int k = 0; k < 2; k++) {
        int e = topi[2 * b + k];
        int s = atomicAdd(&cnt[e], 1);
        list[e * CAP + s] = b;
        slot[2 * b + k] = s;
    }
}

// ---------------- s8 tensor-core GEMM over compacted tokens -------------------
// C[e][slot][N] = A_row(slot) . Bw[e][n][:]  (exact int accumulation)
#define GBM 128
#define GBN 128
#define GBKB 64   // k-bytes per stage
#define SSTR 80   // padded smem row stride in bytes (conflict-free ldmatrix)

__global__ __launch_bounds__(256) void bitgemm_s8_kernel(
    const int8_t* __restrict__ A, long aStrideE,
    const int* __restrict__ gatherList,      // null => A rows are compact slots
    const int* __restrict__ cnts,
    const int8_t* __restrict__ Bw, long bStrideE,
    __half* __restrict__ C, long cStrideE,
    int N, int K)
{
    __shared__ __align__(16) int8_t sA[2][GBM * SSTR];
    __shared__ __align__(16) int8_t sB[2][GBN * SSTR];

    int e = blockIdx.z;
    int cnt = cnts[e];
    int bm = blockIdx.y * GBM;
    if (bm >= cnt) return;
    const int* lst = gatherList ? gatherList + e * CAP : nullptr;

    A  += (long)e * aStrideE;
    Bw += (long)e * bStrideE;
    C  += (long)e * cStrideE;

    int bn = blockIdx.x * GBN;
    int tid = threadIdx.x;
    int lane = tid & 31, warp = tid >> 5;
    int wm = (warp & 1) * 64;    // warp m-offset
    int wn = (warp >> 1) * 32;   // warp n-offset

    // resolve the two A-row global indices this thread loads (fixed across kt)
    long aRow[2];
    #pragma unroll
    for (int i = 0; i < 2; i++) {
        int c = tid + i * 256;
        int row = c >> 2;
        int rr = bm + row;
        if (rr >= cnt) rr = cnt - 1;             // clamp (result rows discarded)
        aRow[i] = lst ? (long)lst[rr] : (long)rr;
    }

    auto loadTiles = [&](int kt, int buf) {
        int k0 = kt * GBKB;
        #pragma unroll
        for (int i = 0; i < 2; i++) {
            int c = tid + i * 256;          // 512 16B chunks per tile
            int row = c >> 2, col = (c & 3) * 16;
            const int8_t* gA = A + aRow[i] * K + k0 + col;
            uint32_t sa = (uint32_t)__cvta_generic_to_shared(&sA[buf][row * SSTR + col]);
            asm volatile("cp.async.cg.shared.global [%0], [%1], 16;\n" :: "r"(sa), "l"(gA));
            const int8_t* gB = Bw + (long)(bn + row) * K + k0 + col;
            uint32_t sb = (uint32_t)__cvta_generic_to_shared(&sB[buf][row * SSTR + col]);
            asm volatile("cp.async.cg.shared.global [%0], [%1], 16;\n" :: "r"(sb), "l"(gB));
        }
        asm volatile("cp.async.commit_group;\n");
    };

    int acc[4][4][4];
    #pragma unroll
    for (int i = 0; i < 4; i++)
        #pragma unroll
        for (int j = 0; j < 4; j++)
            #pragma unroll
            for (int r = 0; r < 4; r++) acc[i][j][r] = 0;

    int KT = K / GBKB;
    loadTiles(0, 0);

    for (int kt = 0; kt < KT; kt++) {
        asm volatile("cp.async.wait_group 0;\n");
        __syncthreads();
        if (kt + 1 < KT) loadTiles(kt + 1, (kt + 1) & 1);
        int buf = kt & 1;

        #pragma unroll
        for (int ks = 0; ks < 2; ks++) {
            int kb = ks * 32;                    // byte offset of this k32 step
            // A fragments: 4 x (16m x 32k s8) via b16-view ldmatrix
            // lanes 0-15 -> rows, col kb; lanes 16-31 -> rows, col kb+16
            uint32_t a[4][4];
            #pragma unroll
            for (int mi = 0; mi < 4; mi++) {
                int row = wm + mi * 16 + (lane & 15);
                int col = kb + (lane >> 4) * 16;
                uint32_t addr = (uint32_t)__cvta_generic_to_shared(&sA[buf][row * SSTR + col]);
                asm volatile("ldmatrix.sync.aligned.m8n8.x4.shared.b16 {%0,%1,%2,%3}, [%4];\n"
                    : "=r"(a[mi][0]), "=r"(a[mi][1]), "=r"(a[mi][2]), "=r"(a[mi][3]) : "r"(addr));
            }
            // B fragments: 2 x (16n x 32k s8)
            // lanes 0-7: n rows 0-7 col kb; 8-15: rows 0-7 col kb+16;
            // 16-23: rows 8-15 col kb; 24-31: rows 8-15 col kb+16
            uint32_t b[2][4];
            #pragma unroll
            for (int j = 0; j < 2; j++) {
                int row = wn + j * 16 + (lane & 7) + ((lane >> 4) << 3);
                int col = kb + ((lane >> 3) & 1) * 16;
                uint32_t addr = (uint32_t)__cvta_generic_to_shared(&sB[buf][row * SSTR + col]);
                asm volatile("ldmatrix.sync.aligned.m8n8.x4.shared.b16 {%0,%1,%2,%3}, [%4];\n"
                    : "=r"(b[j][0]), "=r"(b[j][1]), "=r"(b[j][2]), "=r"(b[j][3]) : "r"(addr));
            }
            #pragma unroll
            for (int mi = 0; mi < 4; mi++) {
                #pragma unroll
                for (int ni = 0; ni < 4; ni++) {
                    uint32_t b0 = b[ni >> 1][(ni & 1) * 2];
                    uint32_t b1 = b[ni >> 1][(ni & 1) * 2 + 1];
                    asm volatile(
                        "mma.sync.aligned.m16n8k32.row.col.s32.s8.s8.s32 "
                        "{%0,%1,%2,%3}, {%4,%5,%6,%7}, {%8,%9}, {%0,%1,%2,%3};\n"
                        : "+r"(acc[mi][ni][0]), "+r"(acc[mi][ni][1]),
                          "+r"(acc[mi][ni][2]), "+r"(acc[mi][ni][3])
                        : "r"(a[mi][0]), "r"(a[mi][1]), "r"(a[mi][2]), "r"(a[mi][3]),
                          "r"(b0), "r"(b1));
                }
            }
        }
    }

    // epilogue: fp16 (values are exact small integers), guard live rows
    #pragma unroll
    for (int mi = 0; mi < 4; mi++) {
        int r0 = bm + wm + mi * 16 + (lane >> 2);
        #pragma unroll
        for (int ni = 0; ni < 4; ni++) {
            int c0 = bn + wn + ni * 8 + (lane & 3) * 2;
            if (r0 < cnt) {
                __half2* p = (__half2*)&C[(long)r0 * N + c0];
                *p = __floats2half2_rn((float)acc[mi][ni][0], (float)acc[mi][ni][1]);
            }
            if (r0 + 8 < cnt) {
                __half2* p = (__half2*)&C[(long)(r0 + 8) * N + c0];
                *p = __floats2half2_rn((float)acc[mi][ni][2], (float)acc[mi][ni][3]);
            }
        }
    }
}

// ---------------- fused LayerNorm + ReLU + sign -> {0,1} s8 -------------------
__global__ __launch_bounds__(256) void ln_relu_sign_kernel(
    const __half* __restrict__ h, const int* __restrict__ cnts,
    const float* __restrict__ g, const float* __restrict__ bia,
    int8_t* __restrict__ out)
{
    long row = blockIdx.x;               // e*CAP + slot
    int e = (int)(row >> 13);            // CAP = 8192
    int slot = (int)(row & (CAP - 1));
    if (slot >= cnts[e]) return;
    const __half2* hr = (const __half2*)(h + row * HID);
    int tid = threadIdx.x;

    float v[8];
    float s = 0.f, s2 = 0.f;
    #pragma unroll
    for (int i = 0; i < 4; i++) {
        float2 x2 = __half22float2(hr[tid + i * 256]);
        v[2 * i] = x2.x; v[2 * i + 1] = x2.y;
        s += x2.x + x2.y; s2 += x2.x * x2.x + x2.y * x2.y;
    }
    #pragma unroll
    for (int o = 16; o; o >>= 1) {
        s  += __shfl_xor_sync(0xffffffffu, s,  o);
        s2 += __shfl_xor_sync(0xffffffffu, s2, o);
    }
    __shared__ float sh[16];
    __shared__ float stats[2];
    int w = tid >> 5;
    if ((tid & 31) == 0) { sh[w] = s; sh[8 + w] = s2; }
    __syncthreads();
    if (tid == 0) {
        float S = 0.f, S2 = 0.f;
        #pragma unroll
        for (int i = 0; i < 8; i++) { S += sh[i]; S2 += sh[8 + i]; }
        float mu  = S * (1.f / HID);
        float var = S2 * (1.f / HID) - mu * mu;
        stats[0] = mu;
        stats[1] = rsqrtf(var + 1e-5f);
    }
    __syncthreads();
    float mu = stats[0], rstd = stats[1];
    const float* ge = g   + (long)e * HID;
    const float* be = bia + (long)e * HID;
    int8_t* orow = out + row * HID;
    #pragma unroll
    for (int i = 0; i < 8; i++) {
        int c = (tid + (i >> 1) * 256) * 2 + (i & 1);
        float y = (v[i] - mu) * rstd * ge[c] + be[c];
        orow[c] = (y > 0.f) ? (int8_t)1 : (int8_t)0;
    }
}

// ---------------- router fp32 GEMM (+bias+relu): C = relu(A*W^T + b) ----------
__global__ __launch_bounds__(256) void ffgemm_relu_kernel(
    const float* __restrict__ A, const float* __restrict__ W,
    const float* __restrict__ bias, float* __restrict__ C,
    int M, int N, int K)
{
    __shared__ float sA[16][68];
    __shared__ float sB[16][68];
    int bm = blockIdx.y * 64, bn = blockIdx.x * 64;
    int tid = threadIdx.x;
    int tx = tid & 15, ty = tid >> 4;
    float acc[4][4] = {};
    for (int k0 = 0; k0 < K; k0 += 16) {
        __syncthreads();
        #pragma unroll
        for (int i = 0; i < 4; i++) {
            int idx = tid + i * 256;
            int m = idx >> 4, kk = idx & 15;
            sA[kk][m] = A[(long)(bm + m) * K + k0 + kk];
            sB[kk][m] = W[(long)(bn + m) * K + k0 + kk];
        }
        __syncthreads();
        #pragma unroll
        for (int kk = 0; kk < 16; kk++) {
            float a4[4], b4[4];
            #pragma unroll
            for (int i = 0; i < 4; i++) { a4[i] = sA[kk][ty * 4 + i]; b4[i] = sB[kk][tx * 4 + i]; }
            #pragma unroll
            for (int i = 0; i < 4; i++)
                #pragma unroll
                for (int j = 0; j < 4; j++) acc[i][j] += a4[i] * b4[j];
        }
    }
    #pragma unroll
    for (int i = 0; i < 4; i++) {
        int r = bm + ty * 4 + i;
        #pragma unroll
        for (int j = 0; j < 4; j++) {
            int cc = bn + tx * 4 + j;
            float vv = acc[i][j] + bias[cc];
            C[(long)r * N + cc] = vv > 0.f ? vv : 0.f;
        }
    }
}

// ---------------- router head: scores, top-2, gates ---------------------------
__global__ __launch_bounds__(256) void router3_top2_kernel(
    const float* __restrict__ r2, const float* __restrict__ Wr3,
    const float* __restrict__ br3, int* __restrict__ topi, float* __restrict__ gate)
{
    __shared__ float wsh[4 * 128];
    __shared__ float bsh[4];
    int tid = threadIdx.x;
    for (int i = tid; i < 4 * 128; i += 256) wsh[i] = Wr3[i];
    if (tid < 4) bsh[tid] = br3[tid];
    __syncthreads();

    int b = blockIdx.x * 256 + tid;
    const float* r = r2 + (long)b * 128;
    float s0 = bsh[0], s1 = bsh[1], s2 = bsh[2], s3 = bsh[3];
    for (int k = 0; k < 128; k++) {
        float rv = r[k];
        s0 += rv * wsh[0 * 128 + k];
        s1 += rv * wsh[1 * 128 + k];
        s2 += rv * wsh[2 * 128 + k];
        s3 += rv * wsh[3 * 128 + k];
    }
    float sc[4] = {s0, s1, s2, s3};
    int i0 = 0; float v0 = sc[0];
    #pragma unroll
    for (int e2 = 1; e2 < 4; e2++) if (sc[e2] > v0) { v0 = sc[e2]; i0 = e2; }
    int i1 = -1; float v1 = 0.f;
    #pragma unroll
    for (int e2 = 0; e2 < 4; e2++) {
        if (e2 == i0) continue;
        if (i1 < 0 || sc[e2] > v1) { v1 = sc[e2]; i1 = e2; }
    }
    float t  = __expf(v1 - v0);          // v1 <= v0
    float g0 = 1.f / (1.f + t);
    float g1 = t * g0;
    topi[2 * b]     = i0;
    topi[2 * b + 1] = i1;
    gate[2 * b]     = g0;
    gate[2 * b + 1] = g1;
}

// ---------------- gate combine (reads compacted eo via slot map) --------------
__global__ __launch_bounds__(256) void combine_kernel(
    const __half* __restrict__ eo, const int* __restrict__ topi,
    const int* __restrict__ slot, const float* __restrict__ gate,
    float* __restrict__ out)
{
    long idx = (long)blockIdx.x * 256 + threadIdx.x;
    if (idx >= (long)B_TOK * NCLS) return;
    int b = (int)(idx / NCLS);
    int c = (int)(idx - (long)b * NCLS);
    int i0 = topi[2 * b], i1 = topi[2 * b + 1];
    int s0 = slot[2 * b], s1 = slot[2 * b + 1];
    float g0 = gate[2 * b], g1 = gate[2 * b + 1];
    float y0 = __half2float(eo[((long)i0 * CAP + s0) * NCLS_P + c]);
    float y1 = __half2float(eo[((long)i1 * CAP + s1) * NCLS_P + c]);
    out[idx] = g0 * y0 + g1 * y1;
}

// ---------------- launch ------------------------------------------------------
extern "C" void kernel_launch(void* const* d_in, const int* in_sizes, int n_in,
                              void* d_out, int out_size)
{
    const float* x   = (const float*)d_in[0];
    const float* Wr1 = (const float*)d_in[1];
    const float* br1 = (const float*)d_in[2];
    const float* Wr2 = (const float*)d_in[3];
    const float* br2 = (const float*)d_in[4];
    const float* Wr3 = (const float*)d_in[5];
    const float* br3 = (const float*)d_in[6];
    const float* W1  = (const float*)d_in[7];
    const float* g1  = (const float*)d_in[8];
    const float* b1  = (const float*)d_in[9];
    const float* W2  = (const float*)d_in[10];
    const float* g2  = (const float*)d_in[11];
    const float* b2  = (const float*)d_in[12];
    const float* W3  = (const float*)d_in[13];
    float* out = (float*)d_out;

    int8_t *xq, *w1q, *w2q, *w3q, *a;
    __half *h, *eo;
    float *r1, *r2, *gate, *partial, *wmean;
    int *topi, *cnt, *list, *slot;
    cudaGetSymbolAddress((void**)&xq,  d_xq);
    cudaGetSymbolAddress((void**)&w1q, d_w1q);
    cudaGetSymbolAddress((void**)&w2q, d_w2q);
    cudaGetSymbolAddress((void**)&w3q, d_w3q);
    cudaGetSymbolAddress((void**)&h,   d_h);
    cudaGetSymbolAddress((void**)&a,   d_a);
    cudaGetSymbolAddress((void**)&eo,  d_eo);
    cudaGetSymbolAddress((void**)&r1,  d_r1);
    cudaGetSymbolAddress((void**)&r2,  d_r2);
    cudaGetSymbolAddress((void**)&topi, d_topi);
    cudaGetSymbolAddress((void**)&gate, d_gate);
    cudaGetSymbolAddress((void**)&cnt,  d_cnt);
    cudaGetSymbolAddress((void**)&list, d_list);
    cudaGetSymbolAddress((void**)&slot, d_slot);
    cudaGetSymbolAddress((void**)&partial, d_partial);
    cudaGetSymbolAddress((void**)&wmean,   d_wmean);

    // 1) weight means (deterministic)
    wsum_partial_kernel<<<dim3(128, 4), 256>>>(W1, (long)HID * IN_DIM, partial + 0);
    wsum_partial_kernel<<<dim3(128, 4), 256>>>(W2, (long)HID * HID,    partial + 512);
    wsum_partial_kernel<<<dim3(128, 4), 256>>>(W3, (long)NCLS * HID,   partial + 1024);
    wmean_final_kernel<<<12, 128>>>(partial, wmean);

    // 2) quantize weights + activations to s8
    {
        long t1 = (long)NEXP * HID * IN_DIM;
        quantW_kernel<<<(int)((t1 + 255) / 256), 256>>>(W1, wmean + 0, HID, HID, IN_DIM, w1q, t1);
        long t2 = (long)NEXP * HID * HID;
        quantW_kernel<<<(int)((t2 + 255) / 256), 256>>>(W2, wmean + 4, HID, HID, HID, w2q, t2);
        long t3 = (long)NEXP * NCLS_P * HID;
        quantW_kernel<<<(int)((t3 + 255) / 256), 256>>>(W3, wmean + 8, NCLS, NCLS_P, HID, w3q, t3);
        long tx = (long)B_TOK * IN_DIM;
        quantX_kernel<<<(int)((tx + 255) / 256), 256>>>(x, xq, tx);
    }

    // 3) router (fp32) + top-2 token lists
    ffgemm_relu_kernel<<<dim3(RH / 64, B_TOK / 64), 256>>>(x,  Wr1, br1, r1, B_TOK, RH,     IN_DIM);
    ffgemm_relu_kernel<<<dim3((RH/2) / 64, B_TOK / 64), 256>>>(r1, Wr2, br2, r2, B_TOK, RH / 2, RH);
    router3_top2_kernel<<<B_TOK / 256, 256>>>(r2, Wr3, br3, topi, gate);
    zero_cnt_kernel<<<1, 32>>>(cnt);
    build_lists_kernel<<<B_TOK / 256, 256>>>(topi, cnt, list, slot);

    // 4) expert stack over selected tokens only (exact s8 integer GEMMs)
    bitgemm_s8_kernel<<<dim3(HID / GBN, CAP / GBM, NEXP), 256>>>(
        xq, 0L, list, cnt, w1q, (long)HID * IN_DIM, h, (long)CAP * HID, HID, IN_DIM);
    ln_relu_sign_kernel<<<NEXP * CAP, 256>>>(h, cnt, g1, b1, a);
    bitgemm_s8_kernel<<<dim3(HID / GBN, CAP / GBM, NEXP), 256>>>(
        a, (long)CAP * HID, nullptr, cnt, w2q, (long)HID * HID, h, (long)CAP * HID, HID, HID);
    ln_relu_sign_kernel<<<NEXP * CAP, 256>>>(h, cnt, g2, b2, a);
    bitgemm_s8_kernel<<<dim3(NCLS_P / GBN, CAP / GBM, NEXP), 256>>>(
        a, (long)CAP * HID, nullptr, cnt, w3q, (long)NCLS_P * HID, eo, (long)CAP * NCLS_P, NCLS_P, HID);

    // 5) combine
    combine_kernel<<<(int)(((long)B_TOK * NCLS + 255) / 256), 256>>>(eo, topi, slot, gate, out);
}

// round 17
// speedup vs baseline: 1.6640x; 1.6640x over previous
#include <cuda_runtime.h>
#include <cuda_bf16.h>
#include <cuda_fp16.h>
#include <cstdint>

// ---------------- problem constants ----------------
#define B_TOK   8192
#define IN_DIM  512
#define HID     2048
#define NCLS    1000
#define NCLS_P  1024      // padded N for layer 3
#define NEXP    4
#define RH      256
#define CAP     8192      // per-expert token capacity

// ---------------- static scratch (no allocs allowed) ----------------
__device__ __nv_bfloat16 d_xq [B_TOK * IN_DIM];                 // sign(x)
__device__ __nv_bfloat16 d_w1q[NEXP * HID * IN_DIM];
__device__ __nv_bfloat16 d_w2q[(long)NEXP * HID * HID];
__device__ __nv_bfloat16 d_w3q[(long)NEXP * NCLS_P * HID];
__device__ __half        d_h  [(long)NEXP * CAP * HID];         // fp16-exact ints
__device__ __nv_bfloat16 d_a  [(long)NEXP * CAP * HID];         // {0,1}
__device__ __half        d_eo [(long)NEXP * CAP * NCLS_P];      // fp16-exact ints
__device__ float         d_r1 [B_TOK * RH];
__device__ float         d_r2 [B_TOK * (RH/2)];
__device__ int           d_topi[B_TOK * 2];
__device__ float         d_gate[B_TOK * 2];
__device__ int           d_cnt [NEXP];
__device__ int           d_list[NEXP * CAP];     // expert -> token ids
__device__ int           d_slot[B_TOK * 2];      // (token,k) -> slot in expert
__device__ float         d_partial[3 * 4 * 128];
__device__ float         d_wmean[12];

// ---------------- weight mean (deterministic 2-stage) ----------------
__global__ __launch_bounds__(256) void wsum_partial_kernel(
    const float* __restrict__ W, long perE, float* __restrict__ partial)
{
    long e = blockIdx.y;
    const float* base = W + e * perE;
    float s = 0.f;
    for (long i = (long)blockIdx.x * 256 + threadIdx.x; i < perE; i += (long)gridDim.x * 256)
        s += base[i];
    #pragma unroll
    for (int o = 16; o; o >>= 1) s += __shfl_xor_sync(0xffffffffu, s, o);
    __shared__ float sh[8];
    if ((threadIdx.x & 31) == 0) sh[threadIdx.x >> 5] = s;
    __syncthreads();
    if (threadIdx.x == 0) {
        float S = 0.f;
        #pragma unroll
        for (int i = 0; i < 8; i++) S += sh[i];
        partial[e * 128 + blockIdx.x] = S;
    }
}

__global__ void wmean_final_kernel(const float* __restrict__ partial, float* __restrict__ wmean)
{
    int bx = blockIdx.x;                 // 12 blocks: layer = bx/4, expert = bx%4
    int layer = bx >> 2;
    const long counts[3] = {(long)HID * IN_DIM, (long)HID * HID, (long)NCLS * HID};
    float s = partial[bx * 128 + threadIdx.x];   // blockDim = 128
    #pragma unroll
    for (int o = 16; o; o >>= 1) s += __shfl_xor_sync(0xffffffffu, s, o);
    __shared__ float sh[4];
    if ((threadIdx.x & 31) == 0) sh[threadIdx.x >> 5] = s;
    __syncthreads();
    if (threadIdx.x == 0)
        wmean[bx] = (sh[0] + sh[1] + sh[2] + sh[3]) / (float)counts[layer];
}

// ---------------- quantize weights: sign(w - mean) -> bf16 (pad rows -> 0) ----
__global__ __launch_bounds__(256) void quantW_kernel(
    const float* __restrict__ w, const float* __restrict__ means,
    int Oin, int Oout, int K, __nv_bfloat16* __restrict__ out, long total)
{
    long i = (long)blockIdx.x * 256 + threadIdx.x;
    if (i >= total) return;
    int k = (int)(i % K);
    long t = i / K;
    int o = (int)(t % Oout);
    int e = (int)(t / Oout);
    float q = 0.f;
    if (o < Oin) {
        float v = w[((long)e * Oin + o) * K + k] - means[e];
        q = (v > 0.f) ? 1.f : ((v < 0.f) ? -1.f : 0.f);
    }
    out[i] = __float2bfloat16(q);
}

__global__ __launch_bounds__(256) void quantX_kernel(
    const float* __restrict__ x, __nv_bfloat16* __restrict__ out, long total)
{
    long i = (long)blockIdx.x * 256 + threadIdx.x;
    if (i >= total) return;
    float v = x[i];
    float q = (v > 0.f) ? 1.f : ((v < 0.f) ? -1.f : 0.f);
    out[i] = __float2bfloat16(q);
}

// ---------------- routing list build ------------------------------------------
__global__ void zero_cnt_kernel(int* cnt) { if (threadIdx.x < NEXP) cnt[threadIdx.x] = 0; }

__global__ __launch_bounds__(256) void build_lists_kernel(
    const int* __restrict__ topi, int* __restrict__ cnt,
    int* __restrict__ list, int* __restrict__ slot)
{
    int b = blockIdx.x * 256 + threadIdx.x;
    if (b >= B_TOK) return;
    #pragma unroll
    for (int k = 0; k < 2; k++) {
        int e = topi[2 * b + k];
        int s = atomicAdd(&cnt[e], 1);
        list[e * CAP + s] = b;
        slot[2 * b + k] = s;
    }
}

// ---------------- bf16 tensor-core GEMM over compacted tokens -----------------
// PROVEN R7 kernel: BM=128, BN=128, BK=32, 2-stage, static smem.
#define GBM 128
#define GBN 128
#define GBK 32
#define GSTR 40   // padded smem row stride in halves (conflict-free ldmatrix)

__global__ __launch_bounds__(256) void bitgemm_kernel(
    const __nv_bfloat16* __restrict__ A, long aStrideE,
    const int* __restrict__ gatherList,      // null => A rows are compact slots
    const int* __restrict__ cnts,
    const __nv_bfloat16* __restrict__ Bw, long bStrideE,
    __half* __restrict__ C, long cStrideE,
    int N, int K)
{
    __shared__ __align__(16) __nv_bfloat16 sA[2][GBM * GSTR];
    __shared__ __align__(16) __nv_bfloat16 sB[2][GBN * GSTR];

    int e = blockIdx.z;
    int cnt = cnts[e];
    int bm = blockIdx.y * GBM;
    if (bm >= cnt) return;
    const int* lst = gatherList ? gatherList + e * CAP : nullptr;

    A  += (long)e * aStrideE;
    Bw += (long)e * bStrideE;
    C  += (long)e * cStrideE;

    int bn = blockIdx.x * GBN;
    int tid = threadIdx.x;
    int lane = tid & 31, warp = tid >> 5;
    int wm = (warp & 1) * 64;    // warp m-offset
    int wn = (warp >> 1) * 32;   // warp n-offset

    // resolve the two A-row global indices this thread loads (fixed across kt)
    long aRow[2];
    #pragma unroll
    for (int i = 0; i < 2; i++) {
        int c = tid + i * 256;
        int row = c >> 2;
        int rr = bm + row;
        if (rr >= cnt) rr = cnt - 1;             // clamp (result rows discarded)
        aRow[i] = lst ? (long)lst[rr] : (long)rr;
    }

    auto loadTiles = [&](int kt, int buf) {
        int k0 = kt * GBK;
        #pragma unroll
        for (int i = 0; i < 2; i++) {
            int c = tid + i * 256;          // 512 16B chunks per tile
            int row = c >> 2, col = (c & 3) * 8;
            const __nv_bfloat16* gA = A + aRow[i] * K + k0 + col;
            uint32_t sa = (uint32_t)__cvta_generic_to_shared(&sA[buf][row * GSTR + col]);
            asm volatile("cp.async.cg.shared.global [%0], [%1], 16;\n" :: "r"(sa), "l"(gA));
            const __nv_bfloat16* gB = Bw + (long)(bn + row) * K + k0 + col;
            uint32_t sb = (uint32_t)__cvta_generic_to_shared(&sB[buf][row * GSTR + col]);
            asm volatile("cp.async.cg.shared.global [%0], [%1], 16;\n" :: "r"(sb), "l"(gB));
        }
        asm volatile("cp.async.commit_group;\n");
    };

    float acc[4][4][4];
    #pragma unroll
    for (int i = 0; i < 4; i++)
        #pragma unroll
        for (int j = 0; j < 4; j++)
            #pragma unroll
            for (int r = 0; r < 4; r++) acc[i][j][r] = 0.f;

    int KT = K / GBK;
    loadTiles(0, 0);

    for (int kt = 0; kt < KT; kt++) {
        asm volatile("cp.async.wait_group 0;\n");
        __syncthreads();
        if (kt + 1 < KT) loadTiles(kt + 1, (kt + 1) & 1);
        int buf = kt & 1;

        #pragma unroll
        for (int ks = 0; ks < 2; ks++) {
            int kb = ks * 16;
            uint32_t a[4][4];
            #pragma unroll
            for (int mi = 0; mi < 4; mi++) {
                int row = wm + mi * 16 + (lane & 15);
                int col = kb + (lane >> 4) * 8;
                uint32_t addr = (uint32_t)__cvta_generic_to_shared(&sA[buf][row * GSTR + col]);
                asm volatile("ldmatrix.sync.aligned.m8n8.x4.shared.b16 {%0,%1,%2,%3}, [%4];\n"
                    : "=r"(a[mi][0]), "=r"(a[mi][1]), "=r"(a[mi][2]), "=r"(a[mi][3]) : "r"(addr));
            }
            uint32_t b[2][4];
            #pragma unroll
            for (int j = 0; j < 2; j++) {
                int row = wn + j * 16 + (lane & 7) + ((lane >> 4) << 3);
                int col = kb + ((lane >> 3) & 1) * 8;
                uint32_t addr = (uint32_t)__cvta_generic_to_shared(&sB[buf][row * GSTR + col]);
                asm volatile("ldmatrix.sync.aligned.m8n8.x4.shared.b16 {%0,%1,%2,%3}, [%4];\n"
                    : "=r"(b[j][0]), "=r"(b[j][1]), "=r"(b[j][2]), "=r"(b[j][3]) : "r"(addr));
            }
            #pragma unroll
            for (int mi = 0; mi < 4; mi++) {
                #pragma unroll
                for (int ni = 0; ni < 4; ni++) {
                    uint32_t b0 = b[ni >> 1][(ni & 1) * 2];
                    uint32_t b1 = b[ni >> 1][(ni & 1) * 2 + 1];
                    asm volatile(
                        "mma.sync.aligned.m16n8k16.row.col.f32.bf16.bf16.f32 "
                        "{%0,%1,%2,%3}, {%4,%5,%6,%7}, {%8,%9}, {%0,%1,%2,%3};\n"
                        : "+f"(acc[mi][ni][0]), "+f"(acc[mi][ni][1]),
                          "+f"(acc[mi][ni][2]), "+f"(acc[mi][ni][3])
                        : "r"(a[mi][0]), "r"(a[mi][1]), "r"(a[mi][2]), "r"(a[mi][3]),
                          "r"(b0), "r"(b1));
                }
            }
        }
    }

    // epilogue: fp16 (values are exact small integers), guard live rows
    #pragma unroll
    for (int mi = 0; mi < 4; mi++) {
        int r0 = bm + wm + mi * 16 + (lane >> 2);
        #pragma unroll
        for (int ni = 0; ni < 4; ni++) {
            int c0 = bn + wn + ni * 8 + (lane & 3) * 2;
            if (r0 < cnt) {
                __half2* p = (__half2*)&C[(long)r0 * N + c0];
                *p = __floats2half2_rn(acc[mi][ni][0], acc[mi][ni][1]);
            }
            if (r0 + 8 < cnt) {
                __half2* p = (__half2*)&C[(long)(r0 + 8) * N + c0];
                *p = __floats2half2_rn(acc[mi][ni][2], acc[mi][ni][3]);
            }
        }
    }
}

// ---------------- fused LayerNorm + ReLU + sign -> {0,1} bf16 -----------------
__global__ __launch_bounds__(256) void ln_relu_sign_kernel(
    const __half* __restrict__ h, const int* __restrict__ cnts,
    const float* __restrict__ g, const float* __restrict__ bia,
    __nv_bfloat16* __restrict__ out)
{
    long row = blockIdx.x;               // e*CAP + slot
    int e = (int)(row >> 13);            // CAP = 8192
    int slot = (int)(row & (CAP - 1));
    if (slot >= cnts[e]) return;
    const __half2* hr = (const __half2*)(h + row * HID);
    int tid = threadIdx.x;

    float v[8];
    float s = 0.f, s2 = 0.f;
    #pragma unroll
    for (int i = 0; i < 4; i++) {
        float2 x2 = __half22float2(hr[tid + i * 256]);
        v[2 * i] = x2.x; v[2 * i + 1] = x2.y;
        s += x2.x + x2.y; s2 += x2.x * x2.x + x2.y * x2.y;
    }
    #pragma unroll
    for (int o = 16; o; o >>= 1) {
        s  += __shfl_xor_sync(0xffffffffu, s,  o);
        s2 += __shfl_xor_sync(0xffffffffu, s2, o);
    }
    __shared__ float sh[16];
    __shared__ float stats[2];
    int w = tid >> 5;
    if ((tid & 31) == 0) { sh[w] = s; sh[8 + w] = s2; }
    __syncthreads();
    if (tid == 0) {
        float S = 0.f, S2 = 0.f;
        #pragma unroll
        for (int i = 0; i < 8; i++) { S += sh[i]; S2 += sh[8 + i]; }
        float mu  = S * (1.f / HID);
        float var = S2 * (1.f / HID) - mu * mu;
        stats[0] = mu;
        stats[1] = rsqrtf(var + 1e-5f);
    }
    __syncthreads();
    float mu = stats[0], rstd = stats[1];
    const float* ge = g   + (long)e * HID;
    const float* be = bia + (long)e * HID;
    __nv_bfloat16* orow = out + row * HID;
    const __nv_bfloat16 one  = __float2bfloat16(1.f);
    const __nv_bfloat16 zero = __float2bfloat16(0.f);
    #pragma unroll
    for (int i = 0; i < 8; i++) {
        int c = (tid + (i >> 1) * 256) * 2 + (i & 1);
        float y = (v[i] - mu) * rstd * ge[c] + be[c];
        orow[c] = (y > 0.f) ? one : zero;
    }
}

// ---------------- router fp32 GEMM (+bias+relu): C = relu(A*W^T + b) ----------
// 128x128 tile, 256 threads, 8x8 per-thread register blocking.
__global__ __launch_bounds__(256) void ffgemm_relu_kernel(
    const float* __restrict__ A, const float* __restrict__ W,
    const float* __restrict__ bias, float* __restrict__ C,
    int M, int N, int K)
{
    __shared__ float sA[16][132];
    __shared__ float sB[16][132];
    int bm = blockIdx.y * 128, bn = blockIdx.x * 128;
    int tid = threadIdx.x;
    int tx = tid & 15, ty = tid >> 4;
    float acc[8][8] = {};
    for (int k0 = 0; k0 < K; k0 += 16) {
        __syncthreads();
        #pragma unroll
        for (int i = 0; i < 8; i++) {
            int idx = tid + i * 256;
            int m = idx >> 4, kk = idx & 15;
            sA[kk][m] = A[(long)(bm + m) * K + k0 + kk];
            sB[kk][m] = W[(long)(bn + m) * K + k0 + kk];
        }
        __syncthreads();
        #pragma unroll
        for (int kk = 0; kk < 16; kk++) {
            float a8[8], b8[8];
            #pragma unroll
            for (int i = 0; i < 8; i++) { a8[i] = sA[kk][ty * 8 + i]; b8[i] = sB[kk][tx * 8 + i]; }
            #pragma unroll
            for (int i = 0; i < 8; i++)
                #pragma unroll
                for (int j = 0; j < 8; j++) acc[i][j] += a8[i] * b8[j];
        }
    }
    #pragma unroll
    for (int i = 0; i < 8; i++) {
        int r = bm + ty * 8 + i;
        #pragma unroll
        for (int j = 0; j < 8; j++) {
            int cc = bn + tx * 8 + j;
            float vv = acc[i][j] + bias[cc];
            C[(long)r * N + cc] = vv > 0.f ? vv : 0.f;
        }
    }
}

// ---------------- router head: scores, top-2, gates ---------------------------
__global__ __launch_bounds__(256) void router3_top2_kernel(
    const float* __restrict__ r2, const float* __restrict__ Wr3,
    const float* __restrict__ br3, int* __restrict__ topi, float* __restrict__ gate)
{
    __shared__ float wsh[4 * 128];
    __shared__ float bsh[4];
    int tid = threadIdx.x;
    for (int i = tid; i < 4 * 128; i += 256) wsh[i] = Wr3[i];
    if (tid < 4) bsh[tid] = br3[tid];
    __syncthreads();

    int b = blockIdx.x * 256 + tid;
    const float* r = r2 + (long)b * 128;
    float s0 = bsh[0], s1 = bsh[1], s2 = bsh[2], s3 = bsh[3];
    for (int k = 0; k < 128; k++) {
        float rv = r[k];
        s0 += rv * wsh[0 * 128 + k];
        s1 += rv * wsh[1 * 128 + k];
        s2 += rv * wsh[2 * 128 + k];
        s3 += rv * wsh[3 * 128 + k];
    }
    float sc[4] = {s0, s1, s2, s3};
    int i0 = 0; float v0 = sc[0];
    #pragma unroll
    for (int e2 = 1; e2 < 4; e2++) if (sc[e2] > v0) { v0 = sc[e2]; i0 = e2; }
    int i1 = -1; float v1 = 0.f;
    #pragma unroll
    for (int e2 = 0; e2 < 4; e2++) {
        if (e2 == i0) continue;
        if (i1 < 0 || sc[e2] > v1) { v1 = sc[e2]; i1 = e2; }
    }
    float t  = __expf(v1 - v0);          // v1 <= v0
    float g0 = 1.f / (1.f + t);
    float g1 = t * g0;
    topi[2 * b]     = i0;
    topi[2 * b + 1] = i1;
    gate[2 * b]     = g0;
    gate[2 * b + 1] = g1;
}

// ---------------- gate combine (reads compacted eo via slot map) --------------
__global__ __launch_bounds__(256) void combine_kernel(
    const __half* __restrict__ eo, const int* __restrict__ topi,
    const int* __restrict__ slot, const float* __restrict__ gate,
    float* __restrict__ out)
{
    long idx = (long)blockIdx.x * 256 + threadIdx.x;
    if (idx >= (long)B_TOK * NCLS) return;
    int b = (int)(idx / NCLS);
    int c = (int)(idx - (long)b * NCLS);
    int i0 = topi[2 * b], i1 = topi[2 * b + 1];
    int s0 = slot[2 * b], s1 = slot[2 * b + 1];
    float g0 = gate[2 * b], g1 = gate[2 * b + 1];
    float y0 = __half2float(eo[((long)i0 * CAP + s0) * NCLS_P + c]);
    float y1 = __half2float(eo[((long)i1 * CAP + s1) * NCLS_P + c]);
    out[idx] = g0 * y0 + g1 * y1;
}

// ---------------- launch ------------------------------------------------------
extern "C" void kernel_launch(void* const* d_in, const int* in_sizes, int n_in,
                              void* d_out, int out_size)
{
    const float* x   = (const float*)d_in[0];
    const float* Wr1 = (const float*)d_in[1];
    const float* br1 = (const float*)d_in[2];
    const float* Wr2 = (const float*)d_in[3];
    const float* br2 = (const float*)d_in[4];
    const float* Wr3 = (const float*)d_in[5];
    const float* br3 = (const float*)d_in[6];
    const float* W1  = (const float*)d_in[7];
    const float* g1  = (const float*)d_in[8];
    const float* b1  = (const float*)d_in[9];
    const float* W2  = (const float*)d_in[10];
    const float* g2  = (const float*)d_in[11];
    const float* b2  = (const float*)d_in[12];
    const float* W3  = (const float*)d_in[13];
    float* out = (float*)d_out;

    __nv_bfloat16 *xq, *w1q, *w2q, *w3q, *a;
    __half *h, *eo;
    float *r1, *r2, *gate, *partial, *wmean;
    int *topi, *cnt, *list, *slot;
    cudaGetSymbolAddress((void**)&xq,  d_xq);
    cudaGetSymbolAddress((void**)&w1q, d_w1q);
    cudaGetSymbolAddress((void**)&w2q, d_w2q);
    cudaGetSymbolAddress((void**)&w3q, d_w3q);
    cudaGetSymbolAddress((void**)&h,   d_h);
    cudaGetSymbolAddress((void**)&a,   d_a);
    cudaGetSymbolAddress((void**)&eo,  d_eo);
    cudaGetSymbolAddress((void**)&r1,  d_r1);
    cudaGetSymbolAddress((void**)&r2,  d_r2);
    cudaGetSymbolAddress((void**)&topi, d_topi);
    cudaGetSymbolAddress((void**)&gate, d_gate);
    cudaGetSymbolAddress((void**)&cnt,  d_cnt);
    cudaGetSymbolAddress((void**)&list, d_list);
    cudaGetSymbolAddress((void**)&slot, d_slot);
    cudaGetSymbolAddress((void**)&partial, d_partial);
    cudaGetSymbolAddress((void**)&wmean,   d_wmean);

    // 1) weight means (deterministic)
    wsum_partial_kernel<<<dim3(128, 4), 256>>>(W1, (long)HID * IN_DIM, partial + 0);
    wsum_partial_kernel<<<dim3(128, 4), 256>>>(W2, (long)HID * HID,    partial + 512);
    wsum_partial_kernel<<<dim3(128, 4), 256>>>(W3, (long)NCLS * HID,   partial + 1024);
    wmean_final_kernel<<<12, 128>>>(partial, wmean);

    // 2) quantize weights + activations (bf16 signs)
    {
        long t1 = (long)NEXP * HID * IN_DIM;
        quantW_kernel<<<(int)((t1 + 255) / 256), 256>>>(W1, wmean + 0, HID, HID, IN_DIM, w1q, t1);
        long t2 = (long)NEXP * HID * HID;
        quantW_kernel<<<(int)((t2 + 255) / 256), 256>>>(W2, wmean + 4, HID, HID, HID, w2q, t2);
        long t3 = (long)NEXP * NCLS_P * HID;
        quantW_kernel<<<(int)((t3 + 255) / 256), 256>>>(W3, wmean + 8, NCLS, NCLS_P, HID, w3q, t3);
        long tx = (long)B_TOK * IN_DIM;
        quantX_kernel<<<(int)((tx + 255) / 256), 256>>>(x, xq, tx);
    }

    // 3) router (fp32) + top-2 token lists
    ffgemm_relu_kernel<<<dim3(RH / 128, B_TOK / 128), 256>>>(x,  Wr1, br1, r1, B_TOK, RH,     IN_DIM);
    ffgemm_relu_kernel<<<dim3((RH/2) / 128, B_TOK / 128), 256>>>(r1, Wr2, br2, r2, B_TOK, RH / 2, RH);
    router3_top2_kernel<<<B_TOK / 256, 256>>>(r2, Wr3, br3, topi, gate);
    zero_cnt_kernel<<<1, 32>>>(cnt);
    build_lists_kernel<<<B_TOK / 256, 256>>>(topi, cnt, list, slot);

    // 4) expert stack over selected tokens only (exact integer GEMMs)
    bitgemm_kernel<<<dim3(HID / GBN, CAP / GBM, NEXP), 256>>>(
        xq, 0L, list, cnt, w1q, (long)HID * IN_DIM, h, (long)CAP * HID, HID, IN_DIM);
    ln_relu_sign_kernel<<<NEXP * CAP, 256>>>(h, cnt, g1, b1, a);
    bitgemm_kernel<<<dim3(HID / GBN, CAP / GBM, NEXP), 256>>>(
        a, (long)CAP * HID, nullptr, cnt, w2q, (long)HID * HID, h, (long)CAP * HID, HID, HID);
    ln_relu_sign_kernel<<<NEXP * CAP, 256>>>(h, cnt, g2, b2, a);
    bitgemm_kernel<<<dim3(NCLS_P / GBN, CAP / GBM, NEXP), 256>>>(
        a, (long)CAP * HID, nullptr, cnt, w3q, (long)NCLS_P * HID, eo, (long)CAP * NCLS_P, NCLS_P, HID);

    // 5) combine
    combine_kernel<<<(int)(((long)B_TOK * NCLS + 255) / 256), 256>>>(eo, topi, slot, gate, out);
}